// round 1
// baseline (speedup 1.0000x reference)
#include <cuda_runtime.h>
#include <cuda_bf16.h>
#include <cstdint>

#define VOCAB   500000
#define EMB_D   128
#define HID     128
#define STEPS   64
#define NROWS   512          // 4*HID gate rows

// ---------------- device globals (scratch; no allocation allowed) ----------
__device__ float               g_K[NROWS];          // folded constant gate bias
__device__ float               g_csT[EMB_D * STEPS];// cs transposed: [k][step]
__device__ unsigned long long  g_best[STEPS];       // packed (enc(score)<<32)|~idx

// ---------------- helpers ---------------------------------------------------
__device__ __forceinline__ uint32_t enc_f32(float f) {
    uint32_t u = __float_as_uint(f);
    return (u & 0x80000000u) ? ~u : (u | 0x80000000u);
}

__device__ __forceinline__ void st_cluster_f32(float* p, uint32_t rank, float v) {
    uint32_t a = (uint32_t)__cvta_generic_to_shared(p);
    uint32_t r;
    asm volatile("mapa.shared::cluster.u32 %0, %1, %2;" : "=r"(r) : "r"(a), "r"(rank));
    asm volatile("st.shared::cluster.f32 [%0], %1;" :: "r"(r), "f"(v) : "memory");
}

__device__ __forceinline__ uint32_t my_cluster_rank() {
    uint32_t r; asm("mov.u32 %0, %%cluster_ctarank;" : "=r"(r)); return r;
}

__device__ __forceinline__ void cluster_sync_all() {
    asm volatile("barrier.cluster.arrive.aligned;" ::: "memory");
    asm volatile("barrier.cluster.wait.aligned;"   ::: "memory");
}

__device__ __forceinline__ float sigf(float x) { return 1.0f / (1.0f + expf(-x)); }

// ============================================================================
// K0: fold constant K[r] = b_ih[r]+b_hh[r] + sum_c W_ih[r][128+c]*inp[c];
//     also zero the per-step argmax accumulators.
// ============================================================================
__global__ void k0_const(const float* __restrict__ inp,
                         const float* __restrict__ w_ih,
                         const float* __restrict__ b_ih,
                         const float* __restrict__ b_hh) {
    int r = threadIdx.x;                 // 512 threads
    if (r < STEPS) g_best[r] = 0ull;
    float s0 = 0.f, s1 = 0.f;
    const float* wr = w_ih + r * 256 + 128;
    #pragma unroll 8
    for (int c = 0; c < 128; c += 2) {
        s0 += wr[c]     * inp[c];
        s1 += wr[c + 1] * inp[c + 1];
    }
    g_K[r] = b_ih[r] + b_hh[r] + s0 + s1;
}

// ============================================================================
// K1: 64 LSTM steps. Cluster of 8 CTAs x 256 threads.
//     CTA `rank` owns hidden indices j = rank*16 .. rank*16+15 (4 gates each
//     -> 64 gate rows). Weights live in registers (64 fp32/thread).
//     State vector xh[256] = [x(=c) ; h] double-buffered, broadcast via DSMEM.
// ============================================================================
__global__ void __launch_bounds__(256, 1)
k1_lstm(const float* __restrict__ embed,
        const float* __restrict__ w_ih,
        const float* __restrict__ w_hh,
        float* __restrict__ out, int write_cs) {
    __shared__ float xh[2][256];
    __shared__ float gates_sm[64];

    const int tid  = threadIdx.x;
    const uint32_t rank = my_cluster_rank();

    const int lr   = tid >> 2;          // local gate row 0..63
    const int part = tid & 3;           // column quarter
    const int g    = lr >> 4;           // gate 0..3
    const int jj   = lr & 15;           // local hidden idx
    const int j    = (int)rank * 16 + jj;
    const int grow = g * 128 + j;       // global gate row

    // ---- preload this thread's 64 weights into registers ----
    float w[64];
    #pragma unroll
    for (int cc = 0; cc < 64; ++cc) {
        int col = part * 64 + cc;
        w[cc] = (col < 128) ? w_ih[grow * 256 + col]
                            : w_hh[grow * 128 + (col - 128)];
    }

    // ---- init state: x = embed[<start>=0], h = 0 ----
    if (tid < 128) {
        xh[0][tid]       = embed[tid];
        xh[0][128 + tid] = 0.f;
    }

    // epilogue-thread registers
    float c_reg = 0.f, k0v = 0.f, k1v = 0.f, k2v = 0.f, k3v = 0.f;
    if (tid < 16) {
        int je = (int)rank * 16 + tid;
        k0v = g_K[je]; k1v = g_K[128 + je]; k2v = g_K[256 + je]; k3v = g_K[384 + je];
    }
    __syncthreads();

    for (int step = 0; step < STEPS; ++step) {
        const int p = step & 1;
        // ---- dot: acc = sum_{cc} w[cc] * xh[p][part*64+cc] ----
        const float4* xv = (const float4*)&xh[p][part * 64];
        float a0 = 0.f, a1 = 0.f, a2 = 0.f, a3 = 0.f;
        #pragma unroll
        for (int q = 0; q < 16; ++q) {
            float4 v = xv[q];
            a0 = fmaf(w[4*q + 0], v.x, a0);
            a1 = fmaf(w[4*q + 1], v.y, a1);
            a2 = fmaf(w[4*q + 2], v.z, a2);
            a3 = fmaf(w[4*q + 3], v.w, a3);
        }
        float acc = (a0 + a1) + (a2 + a3);
        acc += __shfl_xor_sync(0xffffffffu, acc, 1);
        acc += __shfl_xor_sync(0xffffffffu, acc, 2);
        if (part == 0) gates_sm[lr] = acc;
        __syncthreads();

        // ---- epilogue: 16 threads finish their hidden index ----
        if (tid < 16) {
            int je = (int)rank * 16 + tid;
            float gi = gates_sm[ 0 + tid] + k0v;
            float gf = gates_sm[16 + tid] + k1v;
            float gg = gates_sm[32 + tid] + k2v;
            float go = gates_sm[48 + tid] + k3v;
            float iv = sigf(gi), fv = sigf(gf), gv = tanhf(gg), ov = sigf(go);
            float c_new = fv * c_reg + iv * gv;
            float h_new = ov * tanhf(c_new);
            c_reg = c_new;
            if (write_cs) out[step * 128 + je] = c_new;
            g_csT[je * STEPS + step] = c_new;
            // broadcast next-step state to every CTA's other buffer
            const int pn = p ^ 1;
            #pragma unroll
            for (int r = 0; r < 8; ++r) {
                st_cluster_f32(&xh[pn][je],       (uint32_t)r, c_new); // x = c
                st_cluster_f32(&xh[pn][128 + je], (uint32_t)r, h_new);
            }
        }
        cluster_sync_all();   // release DSMEM stores, CTA-wide barrier too
    }
}

// ============================================================================
// K2: scores + argmax. grid = ceil(V/128) CTAs x 256 threads.
//     Tile: 128 rows x 64 steps, K = 128. FFMA2 (fma.rn.f32x2) main loop.
//     smem: ebT[128][129] (transposed+padded), csT[128][64], inv[128].
// ============================================================================
#define EBT_STRIDE 129
#define SMEM_K2_FLOATS (128 * EBT_STRIDE + 128 * 64 + 128)
#define SMEM_K2_BYTES  (SMEM_K2_FLOATS * 4)

__global__ void __launch_bounds__(256, 2)
k2_score(const float* __restrict__ embed, int ntiles) {
    extern __shared__ float sm[];
    float* ebT = sm;                                // 128*129
    float* csT = sm + 128 * EBT_STRIDE;             // 128*64
    float* inv = csT + 128 * 64;                    // 128

    const int tid  = threadIdx.x;
    const int lane = tid & 31;
    const int warp = tid >> 5;
    const int s0   = warp * 8;                      // this warp's 8 steps
    const int tile = blockIdx.x;

    // ---- load embed tile (transposed into smem) ----
    {
        const float4* eg4 = (const float4*)embed;
        for (int i = tid; i < 128 * 32; i += 256) {
            int rloc = i >> 5, k4 = i & 31;
            long long gr = (long long)tile * 128 + rloc;
            float4 v = (gr < VOCAB) ? eg4[gr * 32 + k4]
                                    : make_float4(0.f, 0.f, 0.f, 0.f);
            int kb = k4 * 4;
            ebT[(kb + 0) * EBT_STRIDE + rloc] = v.x;
            ebT[(kb + 1) * EBT_STRIDE + rloc] = v.y;
            ebT[(kb + 2) * EBT_STRIDE + rloc] = v.z;
            ebT[(kb + 3) * EBT_STRIDE + rloc] = v.w;
        }
        const float4* c4 = (const float4*)g_csT;
        float4* d4 = (float4*)csT;
        for (int i = tid; i < (128 * 64) / 4; i += 256) d4[i] = c4[i];
    }
    __syncthreads();

    // ---- row inverse norms (matches ref: 1/max(sqrt(sum),eps)) ----
    if (tid < 128) {
        float s = 0.f, s2 = 0.f;
        #pragma unroll 8
        for (int k = 0; k < 128; k += 2) {
            float v0 = ebT[k * EBT_STRIDE + tid];
            float v1 = ebT[(k + 1) * EBT_STRIDE + tid];
            s = fmaf(v0, v0, s); s2 = fmaf(v1, v1, s2);
        }
        inv[tid] = 1.0f / fmaxf(sqrtf(s + s2), 1e-8f);
    }
    __syncthreads();

    // ---- main GEMM: 4 rows (lane+32i) x 8 steps (s0..s0+7) per thread ----
    unsigned long long acc[4][4];
    #pragma unroll
    for (int i = 0; i < 4; ++i)
        #pragma unroll
        for (int jp = 0; jp < 4; ++jp) acc[i][jp] = 0ull;

    #pragma unroll 4
    for (int k = 0; k < 128; ++k) {
        const unsigned long long* cp =
            (const unsigned long long*)(csT + k * 64 + s0);   // 8B aligned
        unsigned long long c0 = cp[0], c1 = cp[1], c2 = cp[2], c3 = cp[3];
        #pragma unroll
        for (int i = 0; i < 4; ++i) {
            float e = ebT[k * EBT_STRIDE + lane + 32 * i];
            unsigned long long ed;
            asm("mov.b64 %0, {%1, %1};" : "=l"(ed) : "f"(e));
            asm("fma.rn.f32x2 %0, %1, %2, %0;" : "+l"(acc[i][0]) : "l"(ed), "l"(c0));
            asm("fma.rn.f32x2 %0, %1, %2, %0;" : "+l"(acc[i][1]) : "l"(ed), "l"(c1));
            asm("fma.rn.f32x2 %0, %1, %2, %0;" : "+l"(acc[i][2]) : "l"(ed), "l"(c2));
            asm("fma.rn.f32x2 %0, %1, %2, %0;" : "+l"(acc[i][3]) : "l"(ed), "l"(c3));
        }
    }

    // ---- epilogue: per-step best over this thread's 4 rows ----
    float bs[8]; int br[8];
    #pragma unroll
    for (int ss = 0; ss < 8; ++ss) { bs[ss] = -3.4e38f; br[ss] = 0; }
    #pragma unroll
    for (int i = 0; i < 4; ++i) {
        int rloc = lane + 32 * i;
        int gr   = tile * 128 + rloc;
        float iv = inv[rloc];
        #pragma unroll
        for (int jp = 0; jp < 4; ++jp) {
            uint32_t lo32 = (uint32_t)acc[i][jp];
            uint32_t hi32 = (uint32_t)(acc[i][jp] >> 32);
            float sA = __uint_as_float(lo32) * iv;
            float sB = __uint_as_float(hi32) * iv;
            int ss = 2 * jp;
            if (sA > bs[ss])     { bs[ss]     = sA; br[ss]     = gr; }
            if (sB > bs[ss + 1]) { bs[ss + 1] = sB; br[ss + 1] = gr; }
        }
    }
    // warp reduce + global atomic per step
    #pragma unroll
    for (int ss = 0; ss < 8; ++ss) {
        unsigned long long key =
            ((unsigned long long)enc_f32(bs[ss]) << 32) |
            (uint32_t)(~(uint32_t)br[ss]);        // smaller idx wins ties
        #pragma unroll
        for (int off = 16; off; off >>= 1) {
            unsigned long long o = __shfl_xor_sync(0xffffffffu, key, off);
            if (o > key) key = o;
        }
        if (lane == 0) atomicMax(&g_best[s0 + ss], key);
    }
}

// ============================================================================
// K3: decode token ids into the output tail.
// ============================================================================
__global__ void k3_decode(float* __restrict__ out, int out_size) {
    int s = threadIdx.x;
    if (s < STEPS) {
        uint32_t idx = ~((uint32_t)(g_best[s] & 0xffffffffu));
        out[(out_size - STEPS) + s] = (float)idx;
    }
}

// ============================================================================
extern "C" void kernel_launch(void* const* d_in, const int* in_sizes, int n_in,
                              void* d_out, int out_size) {
    const float* inp   = (const float*)d_in[0];
    const float* embed = (const float*)d_in[1];
    const float* w_ih  = (const float*)d_in[2];
    const float* w_hh  = (const float*)d_in[3];
    const float* b_ih  = (const float*)d_in[4];
    const float* b_hh  = (const float*)d_in[5];
    float* out = (float*)d_out;
    (void)in_sizes; (void)n_in;

    const int write_cs = (out_size >= STEPS * 128 + STEPS) ? 1 : 0;

    k0_const<<<1, 512>>>(inp, w_ih, b_ih, b_hh);

    // Phase A: cluster-of-8 LSTM
    {
        cudaLaunchConfig_t cfg = {};
        cfg.gridDim  = dim3(8, 1, 1);
        cfg.blockDim = dim3(256, 1, 1);
        cfg.dynamicSmemBytes = 0;
        cfg.stream = 0;
        cudaLaunchAttribute attrs[1];
        attrs[0].id = cudaLaunchAttributeClusterDimension;
        attrs[0].val.clusterDim.x = 8;
        attrs[0].val.clusterDim.y = 1;
        attrs[0].val.clusterDim.z = 1;
        cfg.attrs = attrs;
        cfg.numAttrs = 1;
        cudaLaunchKernelEx(&cfg, k1_lstm, embed, w_ih, w_hh, out, write_cs);
    }

    // Phase B: one-pass scoring
    cudaFuncSetAttribute(k2_score, cudaFuncAttributeMaxDynamicSharedMemorySize,
                         SMEM_K2_BYTES);
    const int ntiles = (VOCAB + 127) / 128;
    k2_score<<<ntiles, 256, SMEM_K2_BYTES>>>(embed, ntiles);

    k3_decode<<<1, 64>>>(out, out_size);
}

// round 2
// speedup vs baseline: 1.0249x; 1.0249x over previous
#include <cuda_runtime.h>
#include <cuda_bf16.h>
#include <cstdint>

#define VOCAB   500000
#define EMB_D   128
#define HID     128
#define STEPS   64

// ---------------- device globals (scratch; no allocation allowed) ----------
__device__ float               g_cs[STEPS * HID];   // cell states, [step][k]
__device__ unsigned long long  g_best[STEPS];       // packed (enc(score)<<32)|~idx
__device__ int                 g_done = 0;          // last-CTA counter (self-reset)

// ---------------- helpers ---------------------------------------------------
__device__ __forceinline__ uint32_t enc_f32(float f) {
    uint32_t u = __float_as_uint(f);
    return (u & 0x80000000u) ? ~u : (u | 0x80000000u);
}

__device__ __forceinline__ void st_cluster_f32(float* p, uint32_t rank, float v) {
    uint32_t a = (uint32_t)__cvta_generic_to_shared(p);
    uint32_t r;
    asm volatile("mapa.shared::cluster.u32 %0, %1, %2;" : "=r"(r) : "r"(a), "r"(rank));
    asm volatile("st.shared::cluster.f32 [%0], %1;" :: "r"(r), "f"(v) : "memory");
}

__device__ __forceinline__ uint32_t my_cluster_rank() {
    uint32_t r; asm("mov.u32 %0, %%cluster_ctarank;" : "=r"(r)); return r;
}

__device__ __forceinline__ void cluster_sync_all() {
    asm volatile("barrier.cluster.arrive.aligned;" ::: "memory");
    asm volatile("barrier.cluster.wait.aligned;"   ::: "memory");
}

__device__ __forceinline__ float sigf(float x) { return 1.0f / (1.0f + expf(-x)); }

// ============================================================================
// K1: 64 LSTM steps (cluster of 8 CTAs x 256 threads) with the constant-gate
//     fold (old k0) done in-kernel. CTA `rank` owns hidden indices
//     j = rank*16..rank*16+15 (x4 gates = 64 gate rows); weights in registers.
//     State xh[256] = [x(=c); h] double-buffered, broadcast via DSMEM.
// ============================================================================
__global__ void __launch_bounds__(256, 1)
k1_lstm(const float* __restrict__ embed,
        const float* __restrict__ w_ih,
        const float* __restrict__ w_hh,
        const float* __restrict__ inp,
        const float* __restrict__ b_ih,
        const float* __restrict__ b_hh,
        float* __restrict__ out, int write_cs) {
    __shared__ float xh[2][256];
    __shared__ float gates_sm[64];
    __shared__ float Ksm[64];
    __shared__ float inp_sm[128];

    const int tid  = threadIdx.x;
    const uint32_t rank = my_cluster_rank();

    const int lr   = tid >> 2;          // local gate row 0..63
    const int part = tid & 3;           // column quarter
    const int g    = lr >> 4;           // gate 0..3
    const int jj   = lr & 15;           // local hidden idx
    const int j    = (int)rank * 16 + jj;
    const int grow = g * 128 + j;       // global gate row

    // zero the score accumulators for this call (k2 runs strictly after)
    if (rank == 0 && tid < STEPS) g_best[tid] = 0ull;

    // ---- load inp to smem; init state x = embed[<start>=0], h = 0 ----
    if (tid < 128) {
        inp_sm[tid]      = inp[tid];
        xh[0][tid]       = embed[tid];
        xh[0][128 + tid] = 0.f;
    }

    // ---- preload this thread's 64 recurrent weights into registers ----
    float w[64];
    #pragma unroll
    for (int cc = 0; cc < 64; ++cc) {
        int col = part * 64 + cc;
        w[cc] = (col < 128) ? w_ih[grow * 256 + col]
                            : w_hh[grow * 128 + (col - 128)];
    }
    __syncthreads();

    // ---- fold constant K[grow] = b_ih + b_hh + W_ih[:,128:] @ inp ----
    {
        const float* wr = w_ih + grow * 256 + 128 + part * 32;
        float s = 0.f;
        #pragma unroll 8
        for (int c = 0; c < 32; ++c) s = fmaf(wr[c], inp_sm[part * 32 + c], s);
        s += __shfl_xor_sync(0xffffffffu, s, 1);
        s += __shfl_xor_sync(0xffffffffu, s, 2);
        if (part == 0) Ksm[lr] = s + b_ih[grow] + b_hh[grow];
    }
    __syncthreads();

    // epilogue-thread registers
    float c_reg = 0.f, k0v = 0.f, k1v = 0.f, k2v = 0.f, k3v = 0.f;
    if (tid < 16) {
        k0v = Ksm[ 0 + tid]; k1v = Ksm[16 + tid];
        k2v = Ksm[32 + tid]; k3v = Ksm[48 + tid];
    }
    __syncthreads();

    for (int step = 0; step < STEPS; ++step) {
        const int p = step & 1;
        // ---- dot: acc = sum_{cc} w[cc] * xh[p][part*64+cc] ----
        const float4* xv = (const float4*)&xh[p][part * 64];
        float a0 = 0.f, a1 = 0.f, a2 = 0.f, a3 = 0.f;
        #pragma unroll
        for (int q = 0; q < 16; ++q) {
            float4 v = xv[q];
            a0 = fmaf(w[4*q + 0], v.x, a0);
            a1 = fmaf(w[4*q + 1], v.y, a1);
            a2 = fmaf(w[4*q + 2], v.z, a2);
            a3 = fmaf(w[4*q + 3], v.w, a3);
        }
        float acc = (a0 + a1) + (a2 + a3);
        acc += __shfl_xor_sync(0xffffffffu, acc, 1);
        acc += __shfl_xor_sync(0xffffffffu, acc, 2);
        if (part == 0) gates_sm[lr] = acc;
        __syncthreads();

        // ---- epilogue: 16 threads finish their hidden index ----
        if (tid < 16) {
            int je = (int)rank * 16 + tid;
            float gi = gates_sm[ 0 + tid] + k0v;
            float gf = gates_sm[16 + tid] + k1v;
            float gg = gates_sm[32 + tid] + k2v;
            float go = gates_sm[48 + tid] + k3v;
            float iv = sigf(gi), fv = sigf(gf), gv = tanhf(gg), ov = sigf(go);
            float c_new = fv * c_reg + iv * gv;
            float h_new = ov * tanhf(c_new);
            c_reg = c_new;
            if (write_cs) out[step * 128 + je] = c_new;
            g_cs[step * 128 + je] = c_new;
            // broadcast next-step state to every CTA's other buffer
            const int pn = p ^ 1;
            #pragma unroll
            for (int r = 0; r < 8; ++r) {
                st_cluster_f32(&xh[pn][je],       (uint32_t)r, c_new); // x = c
                st_cluster_f32(&xh[pn][128 + je], (uint32_t)r, h_new);
            }
        }
        cluster_sync_all();   // release DSMEM stores + CTA-wide barrier
    }
}

// ============================================================================
// K2: scores + argmax + (last CTA) decode. grid = ceil(V/128) x 256 threads.
//     Tile 128 rows x 64 steps, K=128. All operands LDS64 u64 pairs; the
//     f32x2 lanes carry (even-k, odd-k) partial sums -> final = lo + hi.
//     smem (stride 130): ebR[128][130], csR[64][130], inv[128].
// ============================================================================
#define RS 130
#define K2_SMEM_FLOATS (128 * RS + 64 * RS + 128)
#define K2_SMEM_BYTES  (K2_SMEM_FLOATS * 4)

__global__ void __launch_bounds__(256, 2)
k2_score(const float* __restrict__ embed, float* __restrict__ out, int out_size) {
    extern __shared__ float sm[];
    float* ebR = sm;                    // 128 * 130
    float* csR = sm + 128 * RS;         // 64 * 130
    float* inv = csR + 64 * RS;         // 128

    const int tid  = threadIdx.x;
    const int lane = tid & 31;
    const int warp = tid >> 5;
    const int s0   = warp * 8;          // this warp's 8 steps
    const int tile = blockIdx.x;

    // ---- load embed tile (row-major, float2 stores keep 8B alignment) ----
    {
        const float4* eg4 = (const float4*)embed;
        for (int i = tid; i < 128 * 32; i += 256) {
            int r = i >> 5, k4 = i & 31;
            long long gr = (long long)tile * 128 + r;
            float4 v = (gr < VOCAB) ? eg4[gr * 32 + k4]
                                    : make_float4(0.f, 0.f, 0.f, 0.f);
            float2* d = (float2*)&ebR[r * RS + k4 * 4];
            d[0] = make_float2(v.x, v.y);
            d[1] = make_float2(v.z, v.w);
        }
        const float2* c2 = (const float2*)g_cs;
        for (int i = tid; i < 64 * 64; i += 256) {
            int s = i >> 6, kk = i & 63;
            *(float2*)&csR[s * RS + kk * 2] = c2[s * 64 + kk];
        }
    }
    __syncthreads();

    // ---- row inverse norms: 1/max(sqrt(sum(e^2)), eps) ----
    if (tid < 128) {
        float a = 0.f, b = 0.f;
        const float2* rp = (const float2*)&ebR[tid * RS];
        #pragma unroll 16
        for (int kk = 0; kk < 64; ++kk) {
            float2 v = rp[kk];
            a = fmaf(v.x, v.x, a); b = fmaf(v.y, v.y, b);
        }
        inv[tid] = 1.0f / fmaxf(sqrtf(a + b), 1e-8f);
    }
    __syncthreads();

    // ---- main GEMM: 4 rows (lane+32i) x 8 steps per thread ----
    unsigned long long acc[4][8];
    #pragma unroll
    for (int i = 0; i < 4; ++i)
        #pragma unroll
        for (int s = 0; s < 8; ++s) acc[i][s] = 0ull;

    #pragma unroll 1
    for (int kk = 0; kk < 64; ++kk) {
        unsigned long long c[8], e[4];
        #pragma unroll
        for (int s = 0; s < 8; ++s)
            c[s] = *(const unsigned long long*)&csR[(s0 + s) * RS + 2 * kk];
        #pragma unroll
        for (int i = 0; i < 4; ++i)
            e[i] = *(const unsigned long long*)&ebR[(lane + 32 * i) * RS + 2 * kk];
        #pragma unroll
        for (int i = 0; i < 4; ++i)
            #pragma unroll
            for (int s = 0; s < 8; ++s)
                asm("fma.rn.f32x2 %0, %1, %2, %0;"
                    : "+l"(acc[i][s]) : "l"(e[i]), "l"(c[s]));
    }

    // ---- epilogue: per-step best over this thread's 4 rows ----
    float bs[8]; int br[8];
    #pragma unroll
    for (int s = 0; s < 8; ++s) { bs[s] = -3.4e38f; br[s] = 0; }
    #pragma unroll
    for (int i = 0; i < 4; ++i) {
        int rl = lane + 32 * i;
        int gr = tile * 128 + rl;
        if (gr < VOCAB) {
            float iv = inv[rl];
            #pragma unroll
            for (int s = 0; s < 8; ++s) {
                uint32_t lo32 = (uint32_t)acc[i][s];
                uint32_t hi32 = (uint32_t)(acc[i][s] >> 32);
                float sc = (__uint_as_float(lo32) + __uint_as_float(hi32)) * iv;
                if (sc > bs[s]) { bs[s] = sc; br[s] = gr; }
            }
        }
    }
    #pragma unroll
    for (int s = 0; s < 8; ++s) {
        unsigned long long key =
            ((unsigned long long)enc_f32(bs[s]) << 32) |
            (uint32_t)(~(uint32_t)br[s]);        // smaller idx wins ties
        #pragma unroll
        for (int off = 16; off; off >>= 1) {
            unsigned long long o = __shfl_xor_sync(0xffffffffu, key, off);
            if (o > key) key = o;
        }
        if (lane == 0) atomicMax(&g_best[s0 + s], key);
    }

    // ---- last CTA decodes token ids into the output tail ----
    __shared__ int is_last;
    __threadfence();
    __syncthreads();
    if (tid == 0) {
        int c = atomicAdd(&g_done, 1);
        is_last = (c == (int)gridDim.x - 1);
    }
    __syncthreads();
    if (is_last) {
        if (tid == 0) g_done = 0;            // reset for next call/replay
        __threadfence();                     // acquire: see all atomicMax results
        if (tid < STEPS) {
            uint32_t idx = ~((uint32_t)(g_best[tid] & 0xffffffffu));
            out[(out_size - STEPS) + tid] = (float)idx;
        }
    }
}

// ============================================================================
extern "C" void kernel_launch(void* const* d_in, const int* in_sizes, int n_in,
                              void* d_out, int out_size) {
    const float* inp   = (const float*)d_in[0];
    const float* embed = (const float*)d_in[1];
    const float* w_ih  = (const float*)d_in[2];
    const float* w_hh  = (const float*)d_in[3];
    const float* b_ih  = (const float*)d_in[4];
    const float* b_hh  = (const float*)d_in[5];
    float* out = (float*)d_out;
    (void)in_sizes; (void)n_in;

    const int write_cs = (out_size >= STEPS * 128 + STEPS) ? 1 : 0;

    // Phase A: cluster-of-8 LSTM (constant fold fused in)
    {
        cudaLaunchConfig_t cfg = {};
        cfg.gridDim  = dim3(8, 1, 1);
        cfg.blockDim = dim3(256, 1, 1);
        cfg.dynamicSmemBytes = 0;
        cfg.stream = 0;
        cudaLaunchAttribute attrs[1];
        attrs[0].id = cudaLaunchAttributeClusterDimension;
        attrs[0].val.clusterDim.x = 8;
        attrs[0].val.clusterDim.y = 1;
        attrs[0].val.clusterDim.z = 1;
        cfg.attrs = attrs;
        cfg.numAttrs = 1;
        cudaLaunchKernelEx(&cfg, k1_lstm, embed, w_ih, w_hh, inp, b_ih, b_hh,
                           out, write_cs);
    }

    // Phase B: one-pass scoring + argmax + decode (last-CTA)
    cudaFuncSetAttribute(k2_score, cudaFuncAttributeMaxDynamicSharedMemorySize,
                         K2_SMEM_BYTES);
    const int ntiles = (VOCAB + 127) / 128;
    k2_score<<<ntiles, 256, K2_SMEM_BYTES>>>(embed, out, out_size);
}